// round 15
// baseline (speedup 1.0000x reference)
#include <cuda_runtime.h>
#include <cuda_bf16.h>
#include <cstdint>

#define B_     8
#define S_     1024
#define D_     512
#define H_     8
#define HD_    64
#define FF_    2048
#define STEPS_ 64
#define CAP_   1088
#define MTOK   (B_*S_)     /* 8192 */
#define MDEC   (STEPS_*B_) /* 512 */
#define MALL   (MTOK+MDEC) /* 8704 */
#define KPITCH 36
#define ATTN_SMEM (4*64*KPITCH*4)

// weight split-array offsets (in packed words)
#define OFF_QKV 0
#define OFF_OUT 393216
#define OFF_W1  524288
#define OFF_W2  1048576
#define WTOTAL  1572864

// ---------------- device scratch (no cudaMalloc allowed) ----------------
__device__ float g_qkv [MTOK*1536];
__device__ float g_qkvdec[MDEC*1536];
__device__ float g_attn[MTOK*D_];
__device__ float g_pre [MTOK*D_];
__device__ float g_h   [MTOK*D_];
__device__ float g_hff [MTOK*FF_];
__device__ float g_kc  [B_*CAP_*D_];
__device__ float g_vc  [B_*CAP_*D_];
__device__ float g_dattn[MDEC*D_];
__device__ float g_dpre [MDEC*D_];
__device__ float g_dhb  [MDEC*D_];
__device__ float g_dhff [MDEC*FF_];
__device__ unsigned g_wh[WTOTAL];   // packed bf16 hi pairs of all weights
__device__ unsigned g_wl[WTOTAL];   // packed bf16 lo pairs

// ---------------- reductions ----------------
__device__ __forceinline__ float warpRedSum(float v) {
#pragma unroll
    for (int o = 16; o; o >>= 1) v += __shfl_xor_sync(0xffffffffu, v, o);
    return v;
}

// ---------------- bf16x3 helpers ----------------
__device__ __forceinline__ unsigned pack_bf2(float lo, float hi) {
    unsigned r;
    asm("cvt.rn.bf16x2.f32 %0, %1, %2;" : "=r"(r) : "f"(hi), "f"(lo));
    return r;
}
__device__ __forceinline__ float2 unpack_bf2(unsigned u) {
    __nv_bfloat162 t;
    *(unsigned*)&t = u;
    return make_float2(__bfloat162float(t.x), __bfloat162float(t.y));
}

__device__ __forceinline__ void mma1(unsigned a0, unsigned a1, unsigned a2, unsigned a3,
                                     unsigned b0, unsigned b1, float c[4]) {
    asm volatile(
        "mma.sync.aligned.m16n8k16.row.col.f32.bf16.bf16.f32 "
        "{%0,%1,%2,%3}, {%4,%5,%6,%7}, {%8,%9}, {%0,%1,%2,%3};"
        : "+f"(c[0]), "+f"(c[1]), "+f"(c[2]), "+f"(c[3])
        : "r"(a0), "r"(a1), "r"(a2), "r"(a3), "r"(b0), "r"(b1));
}

__device__ __forceinline__ void mma_bf(const unsigned a[4][4],
                                       const unsigned b[4][2],
                                       float acc[4][4][4])
{
#pragma unroll
    for (int mt = 0; mt < 4; mt++)
#pragma unroll
        for (int nt = 0; nt < 4; nt++)
            mma1(a[mt][0], a[mt][1], a[mt][2], a[mt][3],
                 b[nt][0], b[nt][1], acc[mt][nt]);
}

// ---------------- weight split kernel (fp32 -> packed bf16 hi/lo) ----------
__global__ void __launch_bounds__(256) splitw(const float* __restrict__ src,
                                              unsigned* __restrict__ dh,
                                              unsigned* __restrict__ dl, int npairs)
{
    const int i = blockIdx.x * 256 + threadIdx.x;
    if (i < npairs) {
        float2 v = *(const float2*)(src + 2 * i);
        unsigned h = pack_bf2(v.x, v.y);
        float2 f = unpack_bf2(h);
        dh[i] = h;
        dl[i] = pack_bf2(v.x - f.x, v.y - f.y);
    }
}

// ---------------- SGEMM (NT), bf16x3 MMA, pre-split B ----------------
// BM=BN=128, BK=16, 256 threads (8 warps 2x4), warp tile 64x32.
// B comes pre-split (packed bf16 hi/lo words, K/2 per row).
// KVOUT: 0 none; 3 combined QKV map (rows<MTOK prefill, else decode; C2/A2
// are the decode-side pointers; K/V cols 512..1535 scatter to kc/vc).
template<int BIAS, int RELU, int RES, int KVOUT>
__global__ void __launch_bounds__(256, 2) sgemm_nt(
    const float* __restrict__ A, const float* __restrict__ A2,
    const unsigned* __restrict__ BmH, const unsigned* __restrict__ BmL,
    const float* __restrict__ bias, const float* __restrict__ R,
    float* __restrict__ C, float* __restrict__ C2,
    int M, int N, int K,
    float* __restrict__ kc, float* __restrict__ vc)
{
    __shared__ unsigned AhS[128][12], AlS[128][12];
    __shared__ unsigned BhS[128][12], BlS[128][12];
    const int tid = threadIdx.x;
    const int m0 = blockIdx.y * 128;
    const int n0 = blockIdx.x * 128;
    const int w = tid >> 5, lane = tid & 31;
    const int wm0 = (w >> 2) * 64;
    const int wn0 = (w & 3) * 32;
    const int g = lane >> 2, tq = lane & 3;
    const int lrow = tid >> 2;
    const int lk4  = (tid & 3) * 4;
    const int lk2  = (tid & 3) * 2;
    const int Kw = K >> 1;

    const bool dec = (KVOUT == 3) && (m0 >= MTOK);
    const float* Ab = dec ? (A2 + (size_t)(m0 - MTOK) * K)
                          : (A  + (size_t)m0 * K);
    const float* Ap0 = Ab + (size_t)lrow * K + lk4;
    const float* Ap1 = Ab + (size_t)(lrow + 64) * K + lk4;
    const unsigned* BH0 = BmH + (size_t)(n0 + lrow)      * Kw + lk2;
    const unsigned* BH1 = BmH + (size_t)(n0 + lrow + 64) * Kw + lk2;
    const unsigned* BL0 = BmL + (size_t)(n0 + lrow)      * Kw + lk2;
    const unsigned* BL1 = BmL + (size_t)(n0 + lrow + 64) * Kw + lk2;

    float acc[4][4][4];
#pragma unroll
    for (int i = 0; i < 4; i++)
#pragma unroll
        for (int j = 0; j < 4; j++)
#pragma unroll
            for (int q = 0; q < 4; q++) acc[i][j][q] = 0.f;

    float4 pa0 = *(const float4*)(Ap0);
    float4 pa1 = *(const float4*)(Ap1);
    uint2 pbh0 = *(const uint2*)(BH0);
    uint2 pbh1 = *(const uint2*)(BH1);
    uint2 pbl0 = *(const uint2*)(BL0);
    uint2 pbl1 = *(const uint2*)(BL1);

    for (int k0 = 0; k0 < K; k0 += 16) {
        {   // A: split on the fly; B: direct store of pre-split words
            unsigned h; float2 f;
            h = pack_bf2(pa0.x, pa0.y); f = unpack_bf2(h);
            AhS[lrow][lk2] = h;
            AlS[lrow][lk2] = pack_bf2(pa0.x - f.x, pa0.y - f.y);
            h = pack_bf2(pa0.z, pa0.w); f = unpack_bf2(h);
            AhS[lrow][lk2 + 1] = h;
            AlS[lrow][lk2 + 1] = pack_bf2(pa0.z - f.x, pa0.w - f.y);
            h = pack_bf2(pa1.x, pa1.y); f = unpack_bf2(h);
            AhS[lrow + 64][lk2] = h;
            AlS[lrow + 64][lk2] = pack_bf2(pa1.x - f.x, pa1.y - f.y);
            h = pack_bf2(pa1.z, pa1.w); f = unpack_bf2(h);
            AhS[lrow + 64][lk2 + 1] = h;
            AlS[lrow + 64][lk2 + 1] = pack_bf2(pa1.z - f.x, pa1.w - f.y);
            BhS[lrow][lk2]          = pbh0.x;
            BhS[lrow][lk2 + 1]      = pbh0.y;
            BhS[lrow + 64][lk2]     = pbh1.x;
            BhS[lrow + 64][lk2 + 1] = pbh1.y;
            BlS[lrow][lk2]          = pbl0.x;
            BlS[lrow][lk2 + 1]      = pbl0.y;
            BlS[lrow + 64][lk2]     = pbl1.x;
            BlS[lrow + 64][lk2 + 1] = pbl1.y;
        }
        __syncthreads();
        if (k0 + 16 < K) {
            const int kw = (k0 >> 1) + 8;
            pa0 = *(const float4*)(Ap0 + k0 + 16);
            pa1 = *(const float4*)(Ap1 + k0 + 16);
            pbh0 = *(const uint2*)(BH0 + kw);
            pbh1 = *(const uint2*)(BH1 + kw);
            pbl0 = *(const uint2*)(BL0 + kw);
            pbl1 = *(const uint2*)(BL1 + kw);
        }
        {
            unsigned ah[4][4], bh[4][2];
#pragma unroll
            for (int mt = 0; mt < 4; mt++) {
                const int rA = wm0 + mt * 16 + g;
                ah[mt][0] = AhS[rA][tq];
                ah[mt][1] = AhS[rA + 8][tq];
                ah[mt][2] = AhS[rA][4 + tq];
                ah[mt][3] = AhS[rA + 8][4 + tq];
            }
#pragma unroll
            for (int nt = 0; nt < 4; nt++) {
                const int rB = wn0 + nt * 8 + g;
                bh[nt][0] = BhS[rB][tq];
                bh[nt][1] = BhS[rB][4 + tq];
            }
            mma_bf(ah, bh, acc);
            {
                unsigned bl[4][2];
#pragma unroll
                for (int nt = 0; nt < 4; nt++) {
                    const int rB = wn0 + nt * 8 + g;
                    bl[nt][0] = BlS[rB][tq];
                    bl[nt][1] = BlS[rB][4 + tq];
                }
                mma_bf(ah, bl, acc);
            }
            {
                unsigned al[4][4];
#pragma unroll
                for (int mt = 0; mt < 4; mt++) {
                    const int rA = wm0 + mt * 16 + g;
                    al[mt][0] = AlS[rA][tq];
                    al[mt][1] = AlS[rA + 8][tq];
                    al[mt][2] = AlS[rA][4 + tq];
                    al[mt][3] = AlS[rA + 8][4 + tq];
                }
                mma_bf(al, bh, acc);
            }
        }
        __syncthreads();
    }

#pragma unroll
    for (int nt = 0; nt < 4; nt++) {
        const int col = n0 + wn0 + nt * 8 + tq * 2;
        const float b0v = BIAS ? bias[col] : 0.f;
        const float b1v = BIAS ? bias[col + 1] : 0.f;
#pragma unroll
        for (int mt = 0; mt < 4; mt++) {
#pragma unroll
            for (int rh = 0; rh < 2; rh++) {
                const int row = m0 + wm0 + mt * 16 + g + rh * 8;
                const int rl = dec ? row - MTOK : row;
                float* Cb = dec ? C2 : C;
                float t0 = acc[mt][nt][rh * 2 + 0] + b0v;
                float t1 = acc[mt][nt][rh * 2 + 1] + b1v;
                if (RES) {
                    float2 r = *(const float2*)(R + (size_t)row * N + col);
                    t0 += r.x; t1 += r.y;
                }
                if (RELU) { t0 = fmaxf(t0, 0.f); t1 = fmaxf(t1, 0.f); }
                float2 v; v.x = t0; v.y = t1;
                *(float2*)(Cb + (size_t)rl * N + col) = v;
                if (KVOUT == 3 && col >= 512) {
                    int bb, ss;
                    if (!dec) { bb = rl >> 10; ss = rl & 1023; }
                    else      { bb = rl & 7;   ss = S_ + (rl >> 3); }
                    float* dst = (col < 1024)
                        ? kc + ((size_t)(bb * CAP_ + ss) * 512 + (col - 512))
                        : vc + ((size_t)(bb * CAP_ + ss) * 512 + (col - 1024));
                    *(float2*)dst = v;
                }
            }
        }
    }
}

// ---------------- tensor-core flash attention core ----------------
__device__ __forceinline__ void flash64_mma(
    const float* __restrict__ qbase, size_t qstride,
    const float* __restrict__ kbase, size_t kstride,
    const float* __restrict__ vbase, size_t vstride,
    float* __restrict__ obase, size_t ostride,
    int ntiles, int diagTile, unsigned* sm, int tid)
{
    unsigned* Kh = sm;
    unsigned* Kl = Kh + 64 * KPITCH;
    unsigned* Vh = Kl + 64 * KPITCH;
    unsigned* Vl = Vh + 64 * KPITCH;
    __nv_bfloat16* vhh = (__nv_bfloat16*)Vh;
    __nv_bfloat16* vlh = (__nv_bfloat16*)Vl;

    const int w = tid >> 5, lane = tid & 31;
    const int g = lane >> 2, tq = lane & 3;
    const int wq0 = w * 16;
    const int strow = tid >> 1, sths = tid & 1;

    unsigned qh[4][4], ql[4][4];
    {
        const float* r0p = qbase + (size_t)(wq0 + g) * qstride;
        const float* r1p = qbase + (size_t)(wq0 + g + 8) * qstride;
#pragma unroll
        for (int s = 0; s < 4; s++)
#pragma unroll
            for (int part = 0; part < 4; part++) {
                const float* rp = (part & 1) ? r1p : r0p;
                const int col = 16 * s + ((part >> 1) ? 8 : 0) + 2 * tq;
                float2 v = *(const float2*)(rp + col);
                float x0 = v.x * 0.125f, x1 = v.y * 0.125f;
                unsigned h = pack_bf2(x0, x1);
                float2 f = unpack_bf2(h);
                qh[s][part] = h;
                ql[s][part] = pack_bf2(x0 - f.x, x1 - f.y);
            }
    }

    float oacc[8][4];
#pragma unroll
    for (int j = 0; j < 8; j++)
#pragma unroll
        for (int q = 0; q < 4; q++) oacc[j][q] = 0.f;
    float mrow0 = -1e30f, mrow1 = -1e30f, lrow0 = 0.f, lrow1 = 0.f;

    for (int tile = 0; tile < ntiles; ++tile) {
        const int j0 = tile * 64;
        __syncthreads();
#pragma unroll
        for (int i = 0; i < 8; i++) {
            float4 kv = *(const float4*)(kbase + (size_t)(j0 + strow) * kstride
                                         + sths * 32 + i * 4);
            unsigned h0 = pack_bf2(kv.x, kv.y); float2 f0 = unpack_bf2(h0);
            unsigned h1 = pack_bf2(kv.z, kv.w); float2 f1 = unpack_bf2(h1);
            const int wi = strow * KPITCH + sths * 16 + i * 2;
            Kh[wi] = h0; Kh[wi + 1] = h1;
            Kl[wi]     = pack_bf2(kv.x - f0.x, kv.y - f0.y);
            Kl[wi + 1] = pack_bf2(kv.z - f1.x, kv.w - f1.y);
            float4 vv = *(const float4*)(vbase + (size_t)(j0 + strow) * vstride
                                         + sths * 32 + i * 4);
            const float* vp = (const float*)&vv;
#pragma unroll
            for (int jj = 0; jj < 4; jj++) {
                const int d = sths * 32 + i * 4 + jj;
                __nv_bfloat16 hb = __float2bfloat16(vp[jj]);
                vhh[d * (2 * KPITCH) + strow] = hb;
                vlh[d * (2 * KPITCH) + strow] =
                    __float2bfloat16(vp[jj] - __bfloat162float(hb));
            }
        }
        __syncthreads();

        float sacc[8][4];
#pragma unroll
        for (int j = 0; j < 8; j++)
#pragma unroll
            for (int q = 0; q < 4; q++) sacc[j][q] = 0.f;
#pragma unroll
        for (int s = 0; s < 4; s++)
#pragma unroll
            for (int j = 0; j < 8; j++) {
                const int base = (8 * j + g) * KPITCH + 8 * s + tq;
                unsigned kb0 = Kh[base], kb1 = Kh[base + 4];
                mma1(qh[s][0], qh[s][1], qh[s][2], qh[s][3], kb0, kb1, sacc[j]);
                mma1(ql[s][0], ql[s][1], ql[s][2], ql[s][3], kb0, kb1, sacc[j]);
                unsigned lb0 = Kl[base], lb1 = Kl[base + 4];
                mma1(qh[s][0], qh[s][1], qh[s][2], qh[s][3], lb0, lb1, sacc[j]);
            }

        if (tile == diagTile) {
            const int row0 = wq0 + g, row1 = row0 + 8;
#pragma unroll
            for (int j = 0; j < 8; j++) {
                const int c = 8 * j + 2 * tq;
                if (c > row0)     sacc[j][0] = -1e30f;
                if (c + 1 > row0) sacc[j][1] = -1e30f;
                if (c > row1)     sacc[j][2] = -1e30f;
                if (c + 1 > row1) sacc[j][3] = -1e30f;
            }
        }

        float m0 = -1e30f, m1 = -1e30f;
#pragma unroll
        for (int j = 0; j < 8; j++) {
            m0 = fmaxf(m0, fmaxf(sacc[j][0], sacc[j][1]));
            m1 = fmaxf(m1, fmaxf(sacc[j][2], sacc[j][3]));
        }
        m0 = fmaxf(m0, __shfl_xor_sync(0xffffffffu, m0, 1));
        m0 = fmaxf(m0, __shfl_xor_sync(0xffffffffu, m0, 2));
        m1 = fmaxf(m1, __shfl_xor_sync(0xffffffffu, m1, 1));
        m1 = fmaxf(m1, __shfl_xor_sync(0xffffffffu, m1, 2));
        const float mn0 = fmaxf(mrow0, m0), mn1 = fmaxf(mrow1, m1);
        const float al0 = __expf(mrow0 - mn0), al1 = __expf(mrow1 - mn1);
        float ls0 = 0.f, ls1 = 0.f;
        unsigned ph0[8], ph1[8], pl0[8], pl1[8];
#pragma unroll
        for (int j = 0; j < 8; j++) {
            float p0 = __expf(sacc[j][0] - mn0);
            float p1 = __expf(sacc[j][1] - mn0);
            float p2 = __expf(sacc[j][2] - mn1);
            float p3 = __expf(sacc[j][3] - mn1);
            ls0 += p0 + p1; ls1 += p2 + p3;
            unsigned h = pack_bf2(p0, p1); float2 f = unpack_bf2(h);
            ph0[j] = h; pl0[j] = pack_bf2(p0 - f.x, p1 - f.y);
            h = pack_bf2(p2, p3); f = unpack_bf2(h);
            ph1[j] = h; pl1[j] = pack_bf2(p2 - f.x, p3 - f.y);
        }
        ls0 += __shfl_xor_sync(0xffffffffu, ls0, 1);
        ls0 += __shfl_xor_sync(0xffffffffu, ls0, 2);
        ls1 += __shfl_xor_sync(0xffffffffu, ls1, 1);
        ls1 += __shfl_xor_sync(0xffffffffu, ls1, 2);
        lrow0 = lrow0 * al0 + ls0; mrow0 = mn0;
        lrow1 = lrow1 * al1 + ls1; mrow1 = mn1;
#pragma unroll
        for (int j = 0; j < 8; j++) {
            oacc[j][0] *= al0; oacc[j][1] *= al0;
            oacc[j][2] *= al1; oacc[j][3] *= al1;
        }

#pragma unroll
        for (int s = 0; s < 4; s++) {
            const unsigned a0 = ph0[2 * s],     a1 = ph1[2 * s];
            const unsigned a2 = ph0[2 * s + 1], a3 = ph1[2 * s + 1];
            const unsigned c0 = pl0[2 * s],     c1 = pl1[2 * s];
            const unsigned c2 = pl0[2 * s + 1], c3 = pl1[2 * s + 1];
#pragma unroll
            for (int j = 0; j < 8; j++) {
                const int base = (8 * j + g) * KPITCH + 8 * s + tq;
                unsigned vb0 = Vh[base], vb1 = Vh[base + 4];
                mma1(a0, a1, a2, a3, vb0, vb1, oacc[j]);
                mma1(c0, c1, c2, c3, vb0, vb1, oacc[j]);
                unsigned wl0 = Vl[base], wl1 = Vl[base + 4];
                mma1(a0, a1, a2, a3, wl0, wl1, oacc[j]);
            }
        }
    }

    const float inv0 = 1.f / lrow0, inv1 = 1.f / lrow1;
#pragma unroll
    for (int j = 0; j < 8; j++) {
        float2 v0; v0.x = oacc[j][0] * inv0; v0.y = oacc[j][1] * inv0;
        float2 v1; v1.x = oacc[j][2] * inv1; v1.y = oacc[j][3] * inv1;
        *(float2*)(obase + (size_t)(wq0 + g) * ostride + 8 * j + 2 * tq) = v0;
        *(float2*)(obase + (size_t)(wq0 + g + 8) * ostride + 8 * j + 2 * tq) = v1;
    }
}

__global__ void __launch_bounds__(128, 3) attn_prefill(const float* __restrict__ qkv,
                                                       float* __restrict__ attn)
{
    extern __shared__ unsigned smu[];
    const int b  = blockIdx.y >> 3;
    const int h  = blockIdx.y & 7;
    const int l0 = blockIdx.x * 64;
    const size_t rowbase = (size_t)(b * S_) * 1536;
    flash64_mma(qkv + rowbase + (size_t)l0 * 1536 + h * 64, 1536,
                qkv + rowbase + 512 + h * 64, 1536,
                qkv + rowbase + 1024 + h * 64, 1536,
                attn + (size_t)(b * S_ + l0) * 512 + h * 64, 512,
                (l0 >> 6) + 1, l0 >> 6, smu, threadIdx.x);
}

__global__ void __launch_bounds__(128, 3) attn_decode(const float* __restrict__ qdec,
                                                      const float* __restrict__ kc,
                                                      const float* __restrict__ vc,
                                                      float* __restrict__ dattn)
{
    extern __shared__ unsigned smu[];
    const int b = blockIdx.x >> 3;
    const int h = blockIdx.x & 7;
    flash64_mma(qdec + (size_t)b * 1536 + h * 64, 8 * 1536,
                kc + (size_t)b * CAP_ * 512 + h * 64, 512,
                vc + (size_t)b * CAP_ * 512 + h * 64, 512,
                dattn + (size_t)b * 512 + h * 64, 8 * 512,
                CAP_ / 64, (CAP_ / 64) - 1, smu, threadIdx.x);
}

// ---------------- LayerNorm over rows of 512 ----------------
template<int MODE>
__global__ void __launch_bounds__(256) ln_rows(const float* __restrict__ in,
                                               const float* __restrict__ g,
                                               const float* __restrict__ be,
                                               float* __restrict__ out)
{
    const int r = blockIdx.x;
    const int tid = threadIdx.x;
    const float* row = in + (size_t)r * 512;
    float v0 = row[tid], v1 = row[tid + 256];
    float s  = warpRedSum(v0 + v1);
    float s2 = warpRedSum(v0 * v0 + v1 * v1);
    __shared__ float r1[8], r2[8];
    __shared__ float smu2, srs;
    const int w = tid >> 5, lane = tid & 31;
    if (lane == 0) { r1[w] = s; r2[w] = s2; }
    __syncthreads();
    if (tid == 0) {
        float S = 0.f, S2 = 0.f;
#pragma unroll
        for (int i = 0; i < 8; i++) { S += r1[i]; S2 += r2[i]; }
        float mu  = S * (1.f / 512.f);
        float var = S2 * (1.f / 512.f) - mu * mu;
        smu2 = mu; srs = rsqrtf(var + 1e-5f);
    }
    __syncthreads();
    int orow;
    if (MODE == 0)      orow = r;
    else if (MODE == 1) orow = r + (r >> 10) * 64;
    else                orow = (r & 7) * CAP_ + S_ + (r >> 3);
    float* od = out + (size_t)orow * 512;
    od[tid]       = (v0 - smu2) * srs * g[tid]       + be[tid];
    od[tid + 256] = (v1 - smu2) * srs * g[tid + 256] + be[tid + 256];
}

// ---------------- host launcher ----------------
struct ScratchPtrs {
    float *Qkv, *Qdec, *Attn, *Pre, *Hb, *Hff, *Kc, *Vc;
    float *Dattn, *Dpre, *Dhb, *Dhff;
    unsigned *Wh, *Wl;
    cudaStream_t sDec;
    cudaEvent_t evQkv, evDec;
};

static const ScratchPtrs& get_scratch() {
    static ScratchPtrs p;
    static bool init = false;
    if (!init) {
        cudaGetSymbolAddress((void**)&p.Qkv,  g_qkv);
        cudaGetSymbolAddress((void**)&p.Qdec, g_qkvdec);
        cudaGetSymbolAddress((void**)&p.Attn, g_attn);
        cudaGetSymbolAddress((void**)&p.Pre,  g_pre);
        cudaGetSymbolAddress((void**)&p.Hb,   g_h);
        cudaGetSymbolAddress((void**)&p.Hff,  g_hff);
        cudaGetSymbolAddress((void**)&p.Kc,   g_kc);
        cudaGetSymbolAddress((void**)&p.Vc,   g_vc);
        cudaGetSymbolAddress((void**)&p.Dattn, g_dattn);
        cudaGetSymbolAddress((void**)&p.Dpre,  g_dpre);
        cudaGetSymbolAddress((void**)&p.Dhb,   g_dhb);
        cudaGetSymbolAddress((void**)&p.Dhff,  g_dhff);
        cudaGetSymbolAddress((void**)&p.Wh,   g_wh);
        cudaGetSymbolAddress((void**)&p.Wl,   g_wl);
        cudaFuncSetAttribute(attn_prefill,
                             cudaFuncAttributeMaxDynamicSharedMemorySize, ATTN_SMEM);
        cudaFuncSetAttribute(attn_decode,
                             cudaFuncAttributeMaxDynamicSharedMemorySize, ATTN_SMEM);
        cudaStreamCreateWithFlags(&p.sDec, cudaStreamNonBlocking);
        cudaEventCreateWithFlags(&p.evQkv, cudaEventDisableTiming);
        cudaEventCreateWithFlags(&p.evDec, cudaEventDisableTiming);
        init = true;
    }
    return p;
}

extern "C" void kernel_launch(void* const* d_in, const int* in_sizes, int n_in,
                              void* d_out, int out_size)
{
    (void)in_sizes; (void)n_in; (void)out_size;
    const float* x    = (const float*)d_in[0];
    const float* dx   = (const float*)d_in[1];
    // d_in[2] = causal_mask (bool) — unused, causality computed analytically
    const float* qkvW = (const float*)d_in[3];
    const float* qkvB = (const float*)d_in[4];
    const float* outW = (const float*)d_in[5];
    const float* outB = (const float*)d_in[6];
    const float* w1   = (const float*)d_in[7];
    const float* b1   = (const float*)d_in[8];
    const float* w2   = (const float*)d_in[9];
    const float* b2   = (const float*)d_in[10];
    const float* ln1w = (const float*)d_in[11];
    const float* ln1b = (const float*)d_in[12];
    const float* ln2w = (const float*)d_in[13];
    const float* ln2b = (const float*)d_in[14];
    float* out = (float*)d_out;

    const ScratchPtrs& sp = get_scratch();

    // ---- weight split (bf16 hi/lo), ~4 us total ----
    splitw<<<(393216 + 255) / 256, 256>>>(qkvW, sp.Wh + OFF_QKV, sp.Wl + OFF_QKV, 393216);
    splitw<<<(131072 + 255) / 256, 256>>>(outW, sp.Wh + OFF_OUT, sp.Wl + OFF_OUT, 131072);
    splitw<<<(524288 + 255) / 256, 256>>>(w1,   sp.Wh + OFF_W1,  sp.Wl + OFF_W1,  524288);
    splitw<<<(524288 + 255) / 256, 256>>>(w2,   sp.Wh + OFF_W2,  sp.Wl + OFF_W2,  524288);

    // ---- merged QKV GEMM: prefill + decode rows, seeds both KV regions ----
    sgemm_nt<1,0,0,3><<<dim3(12, 68), 256>>>(
        x, dx, sp.Wh + OFF_QKV, sp.Wl + OFF_QKV, qkvB, nullptr,
        sp.Qkv, sp.Qdec, MALL, 1536, 512, sp.Kc, sp.Vc);

    // ---- fork: decode chain (batched, M=512) on a second stream ----
    cudaEventRecord(sp.evQkv, 0);
    cudaStreamWaitEvent(sp.sDec, sp.evQkv, 0);
    attn_decode<<<64, 128, ATTN_SMEM, sp.sDec>>>(sp.Qdec, sp.Kc, sp.Vc, sp.Dattn);
    sgemm_nt<1,0,1,0><<<dim3(4, 4), 256, 0, sp.sDec>>>(
        sp.Dattn, nullptr, sp.Wh + OFF_OUT, sp.Wl + OFF_OUT, outB, dx,
        sp.Dpre, nullptr, MDEC, 512, 512, nullptr, nullptr);
    ln_rows<0><<<MDEC, 256, 0, sp.sDec>>>(sp.Dpre, ln1w, ln1b, sp.Dhb);
    sgemm_nt<1,1,0,0><<<dim3(16, 4), 256, 0, sp.sDec>>>(
        sp.Dhb, nullptr, sp.Wh + OFF_W1, sp.Wl + OFF_W1, b1, nullptr,
        sp.Dhff, nullptr, MDEC, 2048, 512, nullptr, nullptr);
    sgemm_nt<1,0,1,0><<<dim3(4, 4), 256, 0, sp.sDec>>>(
        sp.Dhff, nullptr, sp.Wh + OFF_W2, sp.Wl + OFF_W2, b2, sp.Dhb,
        sp.Dpre, nullptr, MDEC, 512, 2048, nullptr, nullptr);
    ln_rows<2><<<MDEC, 256, 0, sp.sDec>>>(sp.Dpre, ln2w, ln2b, out);
    cudaEventRecord(sp.evDec, sp.sDec);

    // ---- prefill chain on the main stream ----
    attn_prefill<<<dim3(16, 64), 128, ATTN_SMEM>>>(sp.Qkv, sp.Attn);
    sgemm_nt<1,0,1,0><<<dim3(4, 64), 256>>>(
        sp.Attn, nullptr, sp.Wh + OFF_OUT, sp.Wl + OFF_OUT, outB, x,
        sp.Pre, nullptr, MTOK, 512, 512, nullptr, nullptr);
    ln_rows<0><<<MTOK, 256>>>(sp.Pre, ln1w, ln1b, sp.Hb);
    sgemm_nt<1,1,0,0><<<dim3(16, 64), 256>>>(
        sp.Hb, nullptr, sp.Wh + OFF_W1, sp.Wl + OFF_W1, b1, nullptr,
        sp.Hff, nullptr, MTOK, 2048, 512, nullptr, nullptr);
    sgemm_nt<1,0,1,0><<<dim3(4, 64), 256>>>(
        sp.Hff, nullptr, sp.Wh + OFF_W2, sp.Wl + OFF_W2, b2, sp.Hb,
        sp.Pre, nullptr, MTOK, 512, 2048, nullptr, nullptr);
    ln_rows<1><<<MTOK, 256>>>(sp.Pre, ln2w, ln2b, out);

    // ---- join ----
    cudaStreamWaitEvent(0, sp.evDec, 0);
}